// round 6
// baseline (speedup 1.0000x reference)
#include <cuda_runtime.h>
#include <math.h>

// Problem dims (fixed)
#define BB 2
#define SS 2048
#define DD 1024
#define LL 1024
#define HH 16
#define DHH 64
#define NTOK 4096   // BB*SS
#define BHN 32      // BB*HH

// ---------------- scratch (static device globals; no allocations) ------------
__device__ float g_q [(size_t)NTOK * LL];
__device__ float g_k [(size_t)NTOK * LL];
__device__ float g_v [(size_t)NTOK * LL];
__device__ float g_sc[(size_t)BHN * SS * SS];   // 512 MB scores/attn
__device__ float g_z1[(size_t)NTOK * DD];
__device__ float g_z2[(size_t)NTOK * DD];
__device__ float g_z3[(size_t)NTOK * DD];

// ---------------- 128x128x8 register-blocked SGEMM (row-major NN) ------------
// C[M,N] = A[M,K] @ B[K,N].  M%128==0, N%128==0, K%8==0 required.
__global__ __launch_bounds__(256) void sgemm_nn_128(
    const float* __restrict__ A, const float* __restrict__ Bm, float* __restrict__ C,
    int M, int N, int K)
{
    __shared__ float As[8][128];
    __shared__ float Bs[8][128];
    int tid = threadIdx.x;
    int bx = blockIdx.x, by = blockIdx.y;
    const float* Ab = A + (size_t)by * 128 * K;
    const float* Bb = Bm + (size_t)bx * 128;

    float acc[8][8];
#pragma unroll
    for (int i = 0; i < 8; i++)
#pragma unroll
        for (int j = 0; j < 8; j++) acc[i][j] = 0.f;

    int aRow = tid >> 1, aCol = (tid & 1) * 4;   // 128 rows x 8 cols (float4)
    int bRow = tid >> 5, bCol = (tid & 31) * 4;  // 8 rows x 128 cols (float4)
    int tr = tid >> 4, tc = tid & 15;            // 16x16 threads, 8x8 each

    for (int k0 = 0; k0 < K; k0 += 8) {
        float4 a4 = *reinterpret_cast<const float4*>(Ab + (size_t)aRow * K + k0 + aCol);
        As[aCol + 0][aRow] = a4.x;
        As[aCol + 1][aRow] = a4.y;
        As[aCol + 2][aRow] = a4.z;
        As[aCol + 3][aRow] = a4.w;
        *reinterpret_cast<float4*>(&Bs[bRow][bCol]) =
            *reinterpret_cast<const float4*>(Bb + (size_t)(k0 + bRow) * N + bCol);
        __syncthreads();
#pragma unroll
        for (int k = 0; k < 8; k++) {
            float ra[8], rb[8];
#pragma unroll
            for (int i = 0; i < 8; i++) ra[i] = As[k][tr * 8 + i];
#pragma unroll
            for (int j = 0; j < 8; j++) rb[j] = Bs[k][tc * 8 + j];
#pragma unroll
            for (int i = 0; i < 8; i++)
#pragma unroll
                for (int j = 0; j < 8; j++) acc[i][j] = fmaf(ra[i], rb[j], acc[i][j]);
        }
        __syncthreads();
    }
#pragma unroll
    for (int i = 0; i < 8; i++) {
        float* Cr = C + (size_t)(by * 128 + tr * 8 + i) * N + bx * 128 + tc * 8;
        *reinterpret_cast<float4*>(Cr)     = make_float4(acc[i][0], acc[i][1], acc[i][2], acc[i][3]);
        *reinterpret_cast<float4*>(Cr + 4) = make_float4(acc[i][4], acc[i][5], acc[i][6], acc[i][7]);
    }
}

// ---------------- scores[bh][k][q] = (K_row . Q_row) / 32 --------------------
// Batched NT GEMM: per head, C[m=k_idx][n=q_idx] = sum_d K[m,d]*Q[n,d] * scale
__global__ __launch_bounds__(256) void attn_scores_k(
    const float* __restrict__ gk, const float* __restrict__ gq, float* __restrict__ sc)
{
    int bh = blockIdx.z;
    int b = bh >> 4, h = bh & 15;
    const float* Kp = gk + (size_t)b * SS * LL + h * DHH;
    const float* Qp = gq + (size_t)b * SS * LL + h * DHH;
    float* Cp = sc + (size_t)bh * SS * SS;

    __shared__ float Ks[64][65];
    __shared__ float Qs[64][65];
    int tid = threadIdx.x;
    int m0 = blockIdx.y * 64, n0 = blockIdx.x * 64;
    int lr = tid >> 4, lc = (tid & 15) * 4;

#pragma unroll
    for (int r = lr; r < 64; r += 16) {
        float4 a4 = *reinterpret_cast<const float4*>(Kp + (size_t)(m0 + r) * LL + lc);
        Ks[r][lc] = a4.x; Ks[r][lc + 1] = a4.y; Ks[r][lc + 2] = a4.z; Ks[r][lc + 3] = a4.w;
        float4 b4 = *reinterpret_cast<const float4*>(Qp + (size_t)(n0 + r) * LL + lc);
        Qs[r][lc] = b4.x; Qs[r][lc + 1] = b4.y; Qs[r][lc + 2] = b4.z; Qs[r][lc + 3] = b4.w;
    }
    __syncthreads();

    int tr = tid >> 4, tc = tid & 15;
    float acc[4][4];
#pragma unroll
    for (int i = 0; i < 4; i++)
#pragma unroll
        for (int j = 0; j < 4; j++) acc[i][j] = 0.f;

#pragma unroll 8
    for (int d = 0; d < 64; d++) {
        float ra[4], rb[4];
#pragma unroll
        for (int i = 0; i < 4; i++) ra[i] = Ks[tr * 4 + i][d];
#pragma unroll
        for (int j = 0; j < 4; j++) rb[j] = Qs[tc * 4 + j][d];
#pragma unroll
        for (int i = 0; i < 4; i++)
#pragma unroll
            for (int j = 0; j < 4; j++) acc[i][j] = fmaf(ra[i], rb[j], acc[i][j]);
    }
    const float scale = 0.03125f;  // 1/sqrt(1024)
#pragma unroll
    for (int i = 0; i < 4; i++) {
        float4 o = make_float4(acc[i][0] * scale, acc[i][1] * scale,
                               acc[i][2] * scale, acc[i][3] * scale);
        *reinterpret_cast<float4*>(Cp + (size_t)(m0 + tr * 4 + i) * SS + n0 + tc * 4) = o;
    }
}

// ---------------- row softmax over contiguous rows of length 2048 ------------
__global__ __launch_bounds__(256) void softmax_k(float* __restrict__ sc)
{
    size_t row = blockIdx.x;
    float* p = sc + row * (size_t)SS;
    int tid = threadIdx.x;
    float v[8];
    float m = -1e30f;
#pragma unroll
    for (int i = 0; i < 8; i++) { v[i] = p[tid + i * 256]; m = fmaxf(m, v[i]); }
    __shared__ float red[256];
    red[tid] = m; __syncthreads();
    for (int s2 = 128; s2 > 0; s2 >>= 1) {
        if (tid < s2) red[tid] = fmaxf(red[tid], red[tid + s2]);
        __syncthreads();
    }
    m = red[0]; __syncthreads();
    float sum = 0.f;
#pragma unroll
    for (int i = 0; i < 8; i++) { v[i] = expf(v[i] - m); sum += v[i]; }
    red[tid] = sum; __syncthreads();
    for (int s2 = 128; s2 > 0; s2 >>= 1) {
        if (tid < s2) red[tid] += red[tid + s2];
        __syncthreads();
    }
    float inv = 1.0f / red[0];
#pragma unroll
    for (int i = 0; i < 8; i++) p[tid + i * 256] = v[i] * inv;
}

// ---------------- out[bh][q][v] = sum_k attn[bh][k][q] * V[b][k][h][v] -------
// TN GEMM: C[m=q, n=v] = sum_kk A[kk][m] * B[kk][n].
__global__ __launch_bounds__(256) void attn_out_k(
    const float* __restrict__ attn, const float* __restrict__ gv, float* __restrict__ z)
{
    int bh = blockIdx.z;
    int b = bh >> 4, h = bh & 15;
    const float* Ap = attn + (size_t)bh * SS * SS;
    const float* Vp = gv + (size_t)b * SS * LL + h * DHH;
    float* Cp = z + (size_t)b * SS * DD + h * DHH;
    int m0 = blockIdx.x * 64;

    __shared__ float As[16][64];
    __shared__ float Bs[16][64];
    int tid = threadIdx.x;
    int lr = tid >> 4, lc = (tid & 15) * 4;
    int tr = tid >> 4, tc = tid & 15;

    float acc[4][4];
#pragma unroll
    for (int i = 0; i < 4; i++)
#pragma unroll
        for (int j = 0; j < 4; j++) acc[i][j] = 0.f;

    for (int k0 = 0; k0 < SS; k0 += 16) {
        *reinterpret_cast<float4*>(&As[lr][lc]) =
            *reinterpret_cast<const float4*>(Ap + (size_t)(k0 + lr) * SS + m0 + lc);
        *reinterpret_cast<float4*>(&Bs[lr][lc]) =
            *reinterpret_cast<const float4*>(Vp + (size_t)(k0 + lr) * LL + lc);
        __syncthreads();
#pragma unroll
        for (int kk = 0; kk < 16; kk++) {
            float ra[4], rb[4];
#pragma unroll
            for (int i = 0; i < 4; i++) ra[i] = As[kk][tr * 4 + i];
#pragma unroll
            for (int j = 0; j < 4; j++) rb[j] = Bs[kk][tc * 4 + j];
#pragma unroll
            for (int i = 0; i < 4; i++)
#pragma unroll
                for (int j = 0; j < 4; j++) acc[i][j] = fmaf(ra[i], rb[j], acc[i][j]);
        }
        __syncthreads();
    }
#pragma unroll
    for (int i = 0; i < 4; i++) {
        *reinterpret_cast<float4*>(Cp + (size_t)(m0 + tr * 4 + i) * DD + tc * 4) =
            make_float4(acc[i][0], acc[i][1], acc[i][2], acc[i][3]);
    }
}

// ---------------- L2 row-normalize (rows of 1024) ----------------------------
__global__ __launch_bounds__(256) void l2norm_k(const float* __restrict__ in, float* __restrict__ out)
{
    size_t row = blockIdx.x;
    const float* p = in + row * (size_t)DD;
    float* o = out + row * (size_t)DD;
    int tid = threadIdx.x;
    float4 v = *reinterpret_cast<const float4*>(p + tid * 4);
    float ss = v.x * v.x + v.y * v.y + v.z * v.z + v.w * v.w;
    __shared__ float red[256];
    red[tid] = ss; __syncthreads();
    for (int s2 = 128; s2 > 0; s2 >>= 1) {
        if (tid < s2) red[tid] += red[tid + s2];
        __syncthreads();
    }
    float inv = 1.0f / fmaxf(sqrtf(red[0]), 1e-12f);
    *reinterpret_cast<float4*>(o + tid * 4) =
        make_float4(v.x * inv, v.y * inv, v.z * inv, v.w * inv);
}

// ---------------- L2 row-normalize + exact-erf GELU --------------------------
__device__ __forceinline__ float gelu_exact(float x)
{
    return 0.5f * x * (1.0f + erff(x * 0.7071067811865475f));
}

__global__ __launch_bounds__(256) void l2norm_gelu_k(const float* __restrict__ in, float* __restrict__ out)
{
    size_t row = blockIdx.x;
    const float* p = in + row * (size_t)DD;
    float* o = out + row * (size_t)DD;
    int tid = threadIdx.x;
    float4 v = *reinterpret_cast<const float4*>(p + tid * 4);
    float ss = v.x * v.x + v.y * v.y + v.z * v.z + v.w * v.w;
    __shared__ float red[256];
    red[tid] = ss; __syncthreads();
    for (int s2 = 128; s2 > 0; s2 >>= 1) {
        if (tid < s2) red[tid] += red[tid + s2];
        __syncthreads();
    }
    float inv = 1.0f / fmaxf(sqrtf(red[0]), 1e-12f);
    *reinterpret_cast<float4*>(o + tid * 4) =
        make_float4(gelu_exact(v.x * inv), gelu_exact(v.y * inv),
                    gelu_exact(v.z * inv), gelu_exact(v.w * inv));
}

// ---------------- launch ------------------------------------------------------
extern "C" void kernel_launch(void* const* d_in, const int* in_sizes, int n_in,
                              void* d_out, int out_size)
{
    const float* x   = (const float*)d_in[0];
    const float* Wq  = (const float*)d_in[1];
    const float* Wk  = (const float*)d_in[2];
    const float* Wv  = (const float*)d_in[3];
    const float* Wo  = (const float*)d_in[4];
    const float* Wff = (const float*)d_in[5];
    float* out = (float*)d_out;

    float *q, *k, *v, *sc, *z1, *z2, *z3;
    cudaGetSymbolAddress((void**)&q,  g_q);
    cudaGetSymbolAddress((void**)&k,  g_k);
    cudaGetSymbolAddress((void**)&v,  g_v);
    cudaGetSymbolAddress((void**)&sc, g_sc);
    cudaGetSymbolAddress((void**)&z1, g_z1);
    cudaGetSymbolAddress((void**)&z2, g_z2);
    cudaGetSymbolAddress((void**)&z3, g_z3);

    dim3 gnn(LL / 128, NTOK / 128);  // (8, 32)

    // QKV projections
    sgemm_nn_128<<<gnn, 256>>>(x, Wq, q, NTOK, LL, DD);
    sgemm_nn_128<<<gnn, 256>>>(x, Wk, k, NTOK, LL, DD);
    sgemm_nn_128<<<gnn, 256>>>(x, Wv, v, NTOK, LL, DD);

    // scores[bh][k][q] = K.Q^T / 32
    dim3 gsc(SS / 64, SS / 64, BHN);  // (32, 32, 32)
    attn_scores_k<<<gsc, 256>>>(k, q, sc);

    // softmax over q axis (contiguous rows)
    softmax_k<<<BHN * SS, 256>>>(sc);

    // out = attn^T @ V, merged-head layout
    dim3 gao(SS / 64, 1, BHN);  // (32, 1, 32)
    attn_out_k<<<gao, 256>>>(sc, v, z1);

    // output projection, normalize, FF, normalize+gelu
    sgemm_nn_128<<<gnn, 256>>>(z1, Wo, z2, NTOK, DD, LL);
    l2norm_k<<<NTOK, 256>>>(z2, z2);
    sgemm_nn_128<<<gnn, 256>>>(z2, Wff, z3, NTOK, DD, DD);
    l2norm_gelu_k<<<NTOK, 256>>>(z3, out);
}

// round 12
// speedup vs baseline: 3.6492x; 3.6492x over previous
#include <cuda_runtime.h>
#include <cuda_bf16.h>
#include <math.h>
#include <stdint.h>

#define SS 2048
#define DD 1024
#define NTOK 4096
#define BHN 32

typedef __nv_bfloat16 bf16;

// ---------------- scratch (static device globals; no allocations) ------------
__device__ __align__(16) bf16 g_xhi[(size_t)NTOK * DD], g_xlo[(size_t)NTOK * DD];
__device__ __align__(16) bf16 g_wthi[5][(size_t)DD * DD], g_wtlo[5][(size_t)DD * DD];
__device__ __align__(16) bf16 g_qhi[(size_t)NTOK * DD], g_qlo[(size_t)NTOK * DD];
__device__ __align__(16) bf16 g_khi[(size_t)NTOK * DD], g_klo[(size_t)NTOK * DD];
__device__ __align__(16) float g_f1[(size_t)NTOK * DD];   // v fp32, later z3
__device__ __align__(16) float g_f2[(size_t)NTOK * DD];   // z2
__device__ __align__(16) bf16 g_ehi[(size_t)BHN * SS * SS], g_elo[(size_t)BHN * SS * SS];
__device__ __align__(16) bf16 g_vthi[(size_t)BHN * 64 * SS], g_vtlo[(size_t)BHN * 64 * SS];
__device__ __align__(16) bf16 g_z1hi[(size_t)NTOK * DD], g_z1lo[(size_t)NTOK * DD];
__device__ __align__(16) bf16 g_z2hi[(size_t)NTOK * DD], g_z2lo[(size_t)NTOK * DD];
__device__ __align__(16) float g_rs[(size_t)BHN * SS];

// ---------------- helpers -----------------------------------------------------
__device__ __forceinline__ uint32_t smem_u32(const void* p) {
    uint32_t a;
    asm("{ .reg .u64 t; cvta.to.shared.u64 t, %1; cvt.u32.u64 %0, t; }" : "=r"(a) : "l"(p));
    return a;
}
__device__ __forceinline__ void cp16(uint32_t dst, const void* src) {
    asm volatile("cp.async.cg.shared.global [%0], [%1], 16;" :: "r"(dst), "l"(src));
}
__device__ __forceinline__ void cp_commit() {
    asm volatile("cp.async.commit_group;" ::: "memory");
}
__device__ __forceinline__ void fsplit(float f, bf16& h, bf16& l) {
    h = __float2bfloat16_rn(f);
    l = __float2bfloat16_rn(f - __bfloat162float(h));
}
__device__ __forceinline__ uint32_t pack2(bf16 a, bf16 b) {
    return (uint32_t)__bfloat16_as_ushort(a) | ((uint32_t)__bfloat16_as_ushort(b) << 16);
}

#define MMA16816(d, a, b) \
    asm volatile("mma.sync.aligned.m16n8k16.row.col.f32.bf16.bf16.f32 " \
        "{%0,%1,%2,%3}, {%4,%5,%6,%7}, {%8,%9}, {%0,%1,%2,%3};" \
        : "+f"((d)[0]), "+f"((d)[1]), "+f"((d)[2]), "+f"((d)[3]) \
        : "r"((a)[0]), "r"((a)[1]), "r"((a)[2]), "r"((a)[3]), "r"((b)[0]), "r"((b)[1]))

// ---------------- mma.sync bf16x3 NT GEMM -------------------------------------
// C[m,n] = sum_k A[m,k]*B[n,k]; A,B given as bf16 hi/lo pairs, K-major.
// Block tile 128x64, K chunk 32, 8 warps of 32x32.
// EPI: 0 = fp32 store, 1 = split bf16 hi/lo store, 2 = exp(acc/32) hi/lo + col sums.
#define BM 128
#define BN 64
#define BK 32
#define SASTR 40
#define CSTR 68                               // fp32 stage stride (272B, 16B-aligned rows)
#define ABYTES (BM * SASTR * 2)               // 10240
#define BBYTES (BN * SASTR * 2)               // 5120
#define STAGEB (2 * ABYTES + 2 * BBYTES)      // 30720
#define SMM    (2 * STAGEB)                   // 61440 (also >= 128*68*4 = 34816)

template<int EPI>
__global__ void __launch_bounds__(256) mma_gemm(
    const bf16* __restrict__ Ahi, const bf16* __restrict__ Alo, int lda, size_t sAb, size_t sAh,
    const bf16* __restrict__ Bhi, const bf16* __restrict__ Blo, int ldb, size_t sBb, size_t sBh,
    float* __restrict__ Cf, bf16* __restrict__ Chi, bf16* __restrict__ Clo,
    int ldc, size_t sCb, size_t sCh,
    int K, float* __restrict__ rs)
{
    extern __shared__ char sm[];
    const int tid = threadIdx.x;
    const int wid = tid >> 5, lane = tid & 31;
    const int wm = wid >> 1, wn = wid & 1;
    const int g = lane >> 2, t = lane & 3;
    const int zb = blockIdx.z >> 4, zh = blockIdx.z & 15;
    const int m0 = blockIdx.y * BM, n0 = blockIdx.x * BN;

    const bf16* Ah = Ahi + (size_t)zb * sAb + (size_t)zh * sAh + (size_t)m0 * lda;
    const bf16* Al = Alo + (size_t)zb * sAb + (size_t)zh * sAh + (size_t)m0 * lda;
    const bf16* Bh = Bhi + (size_t)zb * sBb + (size_t)zh * sBh + (size_t)n0 * ldb;
    const bf16* Bl = Blo + (size_t)zb * sBb + (size_t)zh * sBh + (size_t)n0 * ldb;
    uint32_t sb = smem_u32(sm);

    float acc[2][4][4];
#pragma unroll
    for (int i = 0; i < 2; i++)
#pragma unroll
        for (int j = 0; j < 4; j++)
#pragma unroll
            for (int e = 0; e < 4; e++) acc[i][j][e] = 0.f;

    auto load_stage = [&](int st, int k0) {
        uint32_t base = sb + st * STAGEB;
#pragma unroll
        for (int it = 0; it < 2; it++) {
            int c = tid + it * 256;
            int row = c >> 2, seg = c & 3;
            uint32_t d = base + row * (SASTR * 2) + seg * 16;
            cp16(d,          Ah + (size_t)row * lda + k0 + seg * 8);
            cp16(d + ABYTES, Al + (size_t)row * lda + k0 + seg * 8);
        }
        {
            int row = tid >> 2, seg = tid & 3;
            uint32_t d = base + 2 * ABYTES + row * (SASTR * 2) + seg * 16;
            cp16(d,          Bh + (size_t)row * ldb + k0 + seg * 8);
            cp16(d + BBYTES, Bl + (size_t)row * ldb + k0 + seg * 8);
        }
        cp_commit();
    };

    const int NC = K / BK;
    load_stage(0, 0);
    for (int c = 0; c < NC; c++) {
        if (c + 1 < NC) {
            load_stage((c + 1) & 1, (c + 1) * BK);
            asm volatile("cp.async.wait_group 1;" ::: "memory");
        } else {
            asm volatile("cp.async.wait_group 0;" ::: "memory");
        }
        __syncthreads();
        const char* base = sm + (c & 1) * STAGEB;
        const char* pAh = base;
        const char* pAl = base + ABYTES;
        const char* pBh = base + 2 * ABYTES;
        const char* pBl = base + 2 * ABYTES + BBYTES;
#pragma unroll
        for (int ks = 0; ks < BK; ks += 16) {
            uint32_t aH[2][4], aL[2][4], bH[4][2], bL[4][2];
#pragma unroll
            for (int i = 0; i < 2; i++) {
                int rm = wm * 32 + 16 * i + g;
                int o = (rm * SASTR + ks + 2 * t) * 2;
                aH[i][0] = *(const uint32_t*)(pAh + o);
                aH[i][1] = *(const uint32_t*)(pAh + o + 8 * SASTR * 2);
                aH[i][2] = *(const uint32_t*)(pAh + o + 16);
                aH[i][3] = *(const uint32_t*)(pAh + o + 8 * SASTR * 2 + 16);
                aL[i][0] = *(const uint32_t*)(pAl + o);
                aL[i][1] = *(const uint32_t*)(pAl + o + 8 * SASTR * 2);
                aL[i][2] = *(const uint32_t*)(pAl + o + 16);
                aL[i][3] = *(const uint32_t*)(pAl + o + 8 * SASTR * 2 + 16);
            }
#pragma unroll
            for (int j = 0; j < 4; j++) {
                int rn = wn * 32 + 8 * j + g;
                int o = (rn * SASTR + ks + 2 * t) * 2;
                bH[j][0] = *(const uint32_t*)(pBh + o);
                bH[j][1] = *(const uint32_t*)(pBh + o + 16);
                bL[j][0] = *(const uint32_t*)(pBl + o);
                bL[j][1] = *(const uint32_t*)(pBl + o + 16);
            }
#pragma unroll
            for (int i = 0; i < 2; i++)
#pragma unroll
                for (int j = 0; j < 4; j++) {
                    MMA16816(acc[i][j], aH[i], bH[j]);
                    MMA16816(acc[i][j], aH[i], bL[j]);
                    MMA16816(acc[i][j], aL[i], bH[j]);
                }
        }
        __syncthreads();
    }

    // ---------------- epilogue: stage fp32 tile, then coalesced store --------
    float* stg = (float*)sm;
#pragma unroll
    for (int i = 0; i < 2; i++)
#pragma unroll
        for (int j = 0; j < 4; j++) {
            int row = wm * 32 + 16 * i + g, col = wn * 32 + 8 * j + 2 * t;
            float c0 = acc[i][j][0], c1 = acc[i][j][1];
            float c2 = acc[i][j][2], c3 = acc[i][j][3];
            if (EPI == 2) {
                c0 = __expf(c0 * 0.03125f); c1 = __expf(c1 * 0.03125f);
                c2 = __expf(c2 * 0.03125f); c3 = __expf(c3 * 0.03125f);
            }
            stg[row * CSTR + col]           = c0;
            stg[row * CSTR + col + 1]       = c1;
            stg[(row + 8) * CSTR + col]     = c2;
            stg[(row + 8) * CSTR + col + 1] = c3;
        }
    __syncthreads();

    if (EPI == 2 && tid < 64) {
        float s = 0.f;
#pragma unroll 8
        for (int r = 0; r < 128; r++) s += stg[r * CSTR + tid];
        atomicAdd(rs + (size_t)blockIdx.z * SS + n0 + tid, s);
    }
    {
        int row = tid >> 1, cb = (tid & 1) * 32;
        size_t cof = (size_t)zb * sCb + (size_t)zh * sCh + (size_t)(m0 + row) * ldc + n0 + cb;
        if (EPI == 0) {
            float* dst = Cf + cof;
#pragma unroll
            for (int e = 0; e < 8; e++)
                *(float4*)(dst + e * 4) = *(float4*)&stg[row * CSTR + cb + e * 4];
        } else {
            uint32_t hw[16], lw[16];
#pragma unroll
            for (int e = 0; e < 16; e++) {
                float f0 = stg[row * CSTR + cb + 2 * e];
                float f1 = stg[row * CSTR + cb + 2 * e + 1];
                bf16 h0, l0, h1, l1;
                fsplit(f0, h0, l0);
                fsplit(f1, h1, l1);
                hw[e] = pack2(h0, h1);
                lw[e] = pack2(l0, l1);
            }
#pragma unroll
            for (int e = 0; e < 4; e++) {
                *(uint4*)(Chi + cof + 8 * e) =
                    make_uint4(hw[4 * e], hw[4 * e + 1], hw[4 * e + 2], hw[4 * e + 3]);
                *(uint4*)(Clo + cof + 8 * e) =
                    make_uint4(lw[4 * e], lw[4 * e + 1], lw[4 * e + 2], lw[4 * e + 3]);
            }
        }
    }
}

// ---------------- prep / elementwise kernels ----------------------------------
__global__ void splitf_k(const float* __restrict__ in, bf16* __restrict__ hi,
                         bf16* __restrict__ lo) {
    size_t i = ((size_t)blockIdx.x * 256 + threadIdx.x) * 4;
    float4 v = *(const float4*)(in + i);
    bf16 h0, l0, h1, l1, h2, l2, h3, l3;
    fsplit(v.x, h0, l0); fsplit(v.y, h1, l1);
    fsplit(v.z, h2, l2); fsplit(v.w, h3, l3);
    *(uint2*)(hi + i) = make_uint2(pack2(h0, h1), pack2(h2, h3));
    *(uint2*)(lo + i) = make_uint2(pack2(l0, l1), pack2(l2, l3));
}

__global__ void wprep_k(const float* __restrict__ W, bf16* __restrict__ Thi,
                        bf16* __restrict__ Tlo) {
    __shared__ float t[32][33];
    int x = blockIdx.x * 32 + threadIdx.x;
    int y = blockIdx.y * 32 + threadIdx.y;
#pragma unroll
    for (int i = 0; i < 32; i += 8)
        t[threadIdx.y + i][threadIdx.x] = W[(size_t)(y + i) * DD + x];
    __syncthreads();
    x = blockIdx.y * 32 + threadIdx.x;
    y = blockIdx.x * 32 + threadIdx.y;
#pragma unroll
    for (int i = 0; i < 32; i += 8) {
        bf16 h, l;
        fsplit(t[threadIdx.x][threadIdx.y + i], h, l);
        Thi[(size_t)(y + i) * DD + x] = h;
        Tlo[(size_t)(y + i) * DD + x] = l;
    }
}

__global__ void zero_k(float* __restrict__ p, int n) {
    int i = blockIdx.x * 256 + threadIdx.x;
    if (i < n) p[i] = 0.f;
}

// V'[bh][v][k] = V[b][k][h*64+v] / rs[bh][k], split into hi/lo bf16
__global__ void __launch_bounds__(256) vprep_k(const float* __restrict__ v,
                                               const float* __restrict__ rs,
                                               bf16* __restrict__ vthi,
                                               bf16* __restrict__ vtlo) {
    int bh = blockIdx.y, b = bh >> 4, h = bh & 15, k0 = blockIdx.x * 64;
    __shared__ float t[64][65];
    __shared__ float rsi[64];
    int tid = threadIdx.x;
    if (tid < 64) rsi[tid] = 1.0f / rs[(size_t)bh * SS + k0 + tid];
    __syncthreads();
    for (int e = tid; e < 4096; e += 256) {
        int kk = e >> 6, vv = e & 63;
        t[kk][vv] = v[((size_t)(b * SS + k0 + kk)) * DD + h * 64 + vv] * rsi[kk];
    }
    __syncthreads();
    for (int e = tid; e < 4096; e += 256) {
        int vv = e >> 6, kk = e & 63;
        bf16 hh, ll;
        fsplit(t[kk][vv], hh, ll);
        size_t o = (size_t)bh * 64 * SS + (size_t)vv * SS + k0 + kk;
        vthi[o] = hh;
        vtlo[o] = ll;
    }
}

__global__ __launch_bounds__(256) void l2nsplit_k(const float* __restrict__ in,
                                                  bf16* __restrict__ ohi,
                                                  bf16* __restrict__ olo) {
    size_t row = blockIdx.x;
    const float* p = in + row * (size_t)DD;
    int tid = threadIdx.x;
    float4 v = *(const float4*)(p + tid * 4);
    float ss = v.x * v.x + v.y * v.y + v.z * v.z + v.w * v.w;
    __shared__ float red[256];
    red[tid] = ss; __syncthreads();
    for (int s2 = 128; s2 > 0; s2 >>= 1) {
        if (tid < s2) red[tid] += red[tid + s2];
        __syncthreads();
    }
    float inv = 1.0f / fmaxf(sqrtf(red[0]), 1e-12f);
    bf16 h0, l0, h1, l1, h2, l2, h3, l3;
    fsplit(v.x * inv, h0, l0); fsplit(v.y * inv, h1, l1);
    fsplit(v.z * inv, h2, l2); fsplit(v.w * inv, h3, l3);
    *(uint2*)(ohi + row * DD + tid * 4) = make_uint2(pack2(h0, h1), pack2(h2, h3));
    *(uint2*)(olo + row * DD + tid * 4) = make_uint2(pack2(l0, l1), pack2(l2, l3));
}

__device__ __forceinline__ float gelu_exact(float x) {
    return 0.5f * x * (1.0f + erff(x * 0.7071067811865475f));
}

__global__ __launch_bounds__(256) void l2ngelu_k(const float* __restrict__ in,
                                                 float* __restrict__ out) {
    size_t row = blockIdx.x;
    const float* p = in + row * (size_t)DD;
    int tid = threadIdx.x;
    float4 v = *(const float4*)(p + tid * 4);
    float ss = v.x * v.x + v.y * v.y + v.z * v.z + v.w * v.w;
    __shared__ float red[256];
    red[tid] = ss; __syncthreads();
    for (int s2 = 128; s2 > 0; s2 >>= 1) {
        if (tid < s2) red[tid] += red[tid + s2];
        __syncthreads();
    }
    float inv = 1.0f / fmaxf(sqrtf(red[0]), 1e-12f);
    *(float4*)(out + row * DD + tid * 4) =
        make_float4(gelu_exact(v.x * inv), gelu_exact(v.y * inv),
                    gelu_exact(v.z * inv), gelu_exact(v.w * inv));
}

// ---------------- launch ------------------------------------------------------
extern "C" void kernel_launch(void* const* d_in, const int* in_sizes, int n_in,
                              void* d_out, int out_size)
{
    const float* x = (const float*)d_in[0];
    const float* W[5] = {(const float*)d_in[1], (const float*)d_in[2], (const float*)d_in[3],
                         (const float*)d_in[4], (const float*)d_in[5]};
    float* out = (float*)d_out;

    bf16 *xhi, *xlo, *wthi, *wtlo, *qhi, *qlo, *khi, *klo;
    bf16 *ehi, *elo, *vthi, *vtlo, *z1hi, *z1lo, *z2hi, *z2lo;
    float *f1, *f2, *rs;
    cudaGetSymbolAddress((void**)&xhi, g_xhi);   cudaGetSymbolAddress((void**)&xlo, g_xlo);
    cudaGetSymbolAddress((void**)&wthi, g_wthi); cudaGetSymbolAddress((void**)&wtlo, g_wtlo);
    cudaGetSymbolAddress((void**)&qhi, g_qhi);   cudaGetSymbolAddress((void**)&qlo, g_qlo);
    cudaGetSymbolAddress((void**)&khi, g_khi);   cudaGetSymbolAddress((void**)&klo, g_klo);
    cudaGetSymbolAddress((void**)&ehi, g_ehi);   cudaGetSymbolAddress((void**)&elo, g_elo);
    cudaGetSymbolAddress((void**)&vthi, g_vthi); cudaGetSymbolAddress((void**)&vtlo, g_vtlo);
    cudaGetSymbolAddress((void**)&z1hi, g_z1hi); cudaGetSymbolAddress((void**)&z1lo, g_z1lo);
    cudaGetSymbolAddress((void**)&z2hi, g_z2hi); cudaGetSymbolAddress((void**)&z2lo, g_z2lo);
    cudaGetSymbolAddress((void**)&f1, g_f1);     cudaGetSymbolAddress((void**)&f2, g_f2);
    cudaGetSymbolAddress((void**)&rs, g_rs);

    cudaFuncSetAttribute(mma_gemm<0>, cudaFuncAttributeMaxDynamicSharedMemorySize, SMM);
    cudaFuncSetAttribute(mma_gemm<1>, cudaFuncAttributeMaxDynamicSharedMemorySize, SMM);
    cudaFuncSetAttribute(mma_gemm<2>, cudaFuncAttributeMaxDynamicSharedMemorySize, SMM);

    const size_t WSTEP = (size_t)DD * DD;

    // prep: split x, transpose+split weights, zero rs
    splitf_k<<<NTOK * DD / 1024, 256>>>(x, xhi, xlo);
    dim3 tb(32, 8), tg(32, 32);
    for (int i = 0; i < 5; i++)
        wprep_k<<<tg, tb>>>(W[i], wthi + i * WSTEP, wtlo + i * WSTEP);
    zero_k<<<BHN * SS / 256, 256>>>(rs, BHN * SS);

    // QKV projections (q,k split outputs; v fp32)
    dim3 gnn(16, 32, 1);
    mma_gemm<1><<<gnn, 256, SMM>>>(xhi, xlo, DD, 0, 0,
                                   wthi + 0 * WSTEP, wtlo + 0 * WSTEP, DD, 0, 0,
                                   nullptr, qhi, qlo, DD, 0, 0, DD, nullptr);
    mma_gemm<1><<<gnn, 256, SMM>>>(xhi, xlo, DD, 0, 0,
                                   wthi + 1 * WSTEP, wtlo + 1 * WSTEP, DD, 0, 0,
                                   nullptr, khi, klo, DD, 0, 0, DD, nullptr);
    mma_gemm<0><<<gnn, 256, SMM>>>(xhi, xlo, DD, 0, 0,
                                   wthi + 2 * WSTEP, wtlo + 2 * WSTEP, DD, 0, 0,
                                   f1, nullptr, nullptr, DD, 0, 0, DD, nullptr);

    // E^T[bh][q][k] = exp(q.k/32), col sums -> rs[bh][k]
    dim3 gsc(SS / BN, SS / BM, BHN);   // (32, 16, 32)
    mma_gemm<2><<<gsc, 256, SMM>>>(qhi, qlo, DD, (size_t)SS * DD, 64,
                                   khi, klo, DD, (size_t)SS * DD, 64,
                                   nullptr, ehi, elo, SS,
                                   (size_t)16 * SS * SS, (size_t)SS * SS,
                                   64, rs);

    // V' = V / rs (transposed, split)
    vprep_k<<<dim3(SS / 64, BHN), 256>>>(f1, rs, vthi, vtlo);

    // z1[q, h*64+v] = sum_k E^T[q,k] * V'[v,k]
    dim3 gao(1, SS / BM, BHN);         // (1, 16, 32)
    mma_gemm<1><<<gao, 256, SMM>>>(ehi, elo, SS, (size_t)16 * SS * SS, (size_t)SS * SS,
                                   vthi, vtlo, SS, (size_t)16 * 64 * SS, (size_t)64 * SS,
                                   nullptr, z1hi, z1lo, DD, (size_t)SS * DD, 64,
                                   SS, nullptr);

    // output projection -> z2 (fp32), normalize+split, FF -> z3 (fp32), norm+gelu
    mma_gemm<0><<<gnn, 256, SMM>>>(z1hi, z1lo, DD, 0, 0,
                                   wthi + 3 * WSTEP, wtlo + 3 * WSTEP, DD, 0, 0,
                                   f2, nullptr, nullptr, DD, 0, 0, DD, nullptr);
    l2nsplit_k<<<NTOK, 256>>>(f2, z2hi, z2lo);
    mma_gemm<0><<<gnn, 256, SMM>>>(z2hi, z2lo, DD, 0, 0,
                                   wthi + 4 * WSTEP, wtlo + 4 * WSTEP, DD, 0, 0,
                                   f1, nullptr, nullptr, DD, 0, 0, DD, nullptr);
    l2ngelu_k<<<NTOK, 256>>>(f1, out);
}

// round 13
// speedup vs baseline: 4.1850x; 1.1468x over previous
#include <cuda_runtime.h>
#include <cuda_bf16.h>
#include <math.h>
#include <stdint.h>

#define SS 2048
#define DD 1024
#define NTOK 4096
#define BHN 32

typedef __nv_bfloat16 bf16;

// ---------------- scratch (static device globals; no allocations) ------------
__device__ __align__(16) bf16 g_xhi[(size_t)NTOK * DD], g_xlo[(size_t)NTOK * DD];
__device__ __align__(16) bf16 g_wthi[5][(size_t)DD * DD], g_wtlo[5][(size_t)DD * DD];
__device__ __align__(16) bf16 g_qhi[(size_t)NTOK * DD], g_qlo[(size_t)NTOK * DD];
__device__ __align__(16) bf16 g_khi[(size_t)NTOK * DD], g_klo[(size_t)NTOK * DD];
__device__ __align__(16) float g_f1[(size_t)NTOK * DD];   // v fp32, later z3
__device__ __align__(16) float g_f2[(size_t)NTOK * DD];   // z2
__device__ __align__(16) bf16 g_ehi[(size_t)BHN * SS * SS], g_elo[(size_t)BHN * SS * SS];
__device__ __align__(16) bf16 g_vthi[(size_t)BHN * 64 * SS], g_vtlo[(size_t)BHN * 64 * SS];
__device__ __align__(16) bf16 g_z1hi[(size_t)NTOK * DD], g_z1lo[(size_t)NTOK * DD];
__device__ __align__(16) bf16 g_z2hi[(size_t)NTOK * DD], g_z2lo[(size_t)NTOK * DD];
__device__ __align__(16) float g_rs[(size_t)BHN * SS];

// ---------------- helpers -----------------------------------------------------
__device__ __forceinline__ uint32_t smem_u32(const void* p) {
    uint32_t a;
    asm("{ .reg .u64 t; cvta.to.shared.u64 t, %1; cvt.u32.u64 %0, t; }" : "=r"(a) : "l"(p));
    return a;
}
__device__ __forceinline__ void cp16(uint32_t dst, const void* src) {
    asm volatile("cp.async.cg.shared.global [%0], [%1], 16;" :: "r"(dst), "l"(src));
}
__device__ __forceinline__ void cp_commit() {
    asm volatile("cp.async.commit_group;" ::: "memory");
}
__device__ __forceinline__ void fsplit(float f, bf16& h, bf16& l) {
    h = __float2bfloat16_rn(f);
    l = __float2bfloat16_rn(f - __bfloat162float(h));
}
__device__ __forceinline__ uint32_t pack2(bf16 a, bf16 b) {
    return (uint32_t)__bfloat16_as_ushort(a) | ((uint32_t)__bfloat16_as_ushort(b) << 16);
}

#define MMA16816(d, a, b) \
    asm volatile("mma.sync.aligned.m16n8k16.row.col.f32.bf16.bf16.f32 " \
        "{%0,%1,%2,%3}, {%4,%5,%6,%7}, {%8,%9}, {%0,%1,%2,%3};" \
        : "+f"((d)[0]), "+f"((d)[1]), "+f"((d)[2]), "+f"((d)[3]) \
        : "r"((a)[0]), "r"((a)[1]), "r"((a)[2]), "r"((a)[3]), "r"((b)[0]), "r"((b)[1]))

#define LDSM4(r0, r1, r2, r3, a) \
    asm volatile("ldmatrix.sync.aligned.m8n8.x4.shared.b16 {%0,%1,%2,%3}, [%4];" \
        : "=r"(r0), "=r"(r1), "=r"(r2), "=r"(r3) : "r"(a))

// ---------------- mma.sync bf16x3 NT GEMM -------------------------------------
// C[m,n] = sum_k A[m,k]*B[n,k]; A,B given as bf16 hi/lo pairs, K-major.
// Block tile 128x64, K chunk 32, 8 warps of 32x32, ldmatrix fragments,
// swizzled 128B smem rows [hi 32 half | lo 32 half], 3-stage cp.async.
// EPI: 0 = fp32 store, 1 = split bf16 hi/lo store, 2 = exp(acc/32) hi/lo + col sums.
#define BM 128
#define BN 64
#define BK 32
#define CSTR 68                               // fp32 stage stride (272B, 16B-aligned)
#define STAGE 24576                           // 128*128 (A) + 64*128 (B)
#define SMM   (3 * STAGE)                     // 73728 (also >= 128*68*4 = 34816)

template<int EPI>
__global__ void __launch_bounds__(256) mma_gemm(
    const bf16* __restrict__ Ahi, const bf16* __restrict__ Alo, int lda, size_t sAb, size_t sAh,
    const bf16* __restrict__ Bhi, const bf16* __restrict__ Blo, int ldb, size_t sBb, size_t sBh,
    float* __restrict__ Cf, bf16* __restrict__ Chi, bf16* __restrict__ Clo,
    int ldc, size_t sCb, size_t sCh,
    int K, float* __restrict__ rs)
{
    extern __shared__ __align__(128) char sm[];
    const int tid = threadIdx.x;
    const int wid = tid >> 5, lane = tid & 31;
    const int wm = wid >> 1, wn = wid & 1;
    const int g = lane >> 2, t = lane & 3;
    const int zb = blockIdx.z >> 4, zh = blockIdx.z & 15;
    const int m0 = blockIdx.y * BM, n0 = blockIdx.x * BN;

    const bf16* Ah = Ahi + (size_t)zb * sAb + (size_t)zh * sAh + (size_t)m0 * lda;
    const bf16* Al = Alo + (size_t)zb * sAb + (size_t)zh * sAh + (size_t)m0 * lda;
    const bf16* Bh = Bhi + (size_t)zb * sBb + (size_t)zh * sBh + (size_t)n0 * ldb;
    const bf16* Bl = Blo + (size_t)zb * sBb + (size_t)zh * sBh + (size_t)n0 * ldb;
    const uint32_t sb = smem_u32(sm);

    float acc[2][4][4];
#pragma unroll
    for (int i = 0; i < 2; i++)
#pragma unroll
        for (int j = 0; j < 4; j++)
#pragma unroll
            for (int e = 0; e < 4; e++) acc[i][j][e] = 0.f;

    // ldmatrix base offsets (per thread, stage-relative)
    uint32_t offA[2], offB[2];
    {
        int tile = lane >> 3, lrow = lane & 7;
#pragma unroll
        for (int i = 0; i < 2; i++) {
            int m = wm * 32 + i * 16 + (tile & 1) * 8 + lrow;
            offA[i] = m * 128 + (((tile >> 1) ^ (m & 7)) << 4);
        }
#pragma unroll
        for (int jp = 0; jp < 2; jp++) {
            int n = wn * 32 + jp * 16 + (tile >> 1) * 8 + lrow;
            offB[jp] = 16384 + n * 128 + (((tile & 1) ^ (n & 7)) << 4);
        }
    }

    auto load_stage = [&](int st, int k0) {
        uint32_t base = sb + st * STAGE;
#pragma unroll
        for (int q = 0; q < 4; q++) {           // A: 1024 16B chunks
            int cid = q * 256 + tid;
            int m = cid >> 3, c = cid & 7;
            uint32_t dst = base + m * 128 + (((c ^ (m & 7)) & 7) << 4);
            const bf16* src = (c < 4) ? (Ah + (size_t)m * lda + k0 + c * 8)
                                      : (Al + (size_t)m * lda + k0 + (c - 4) * 8);
            cp16(dst, src);
        }
#pragma unroll
        for (int q = 0; q < 2; q++) {           // B: 512 16B chunks
            int cid = q * 256 + tid;
            int n = cid >> 3, c = cid & 7;
            uint32_t dst = base + 16384 + n * 128 + (((c ^ (n & 7)) & 7) << 4);
            const bf16* src = (c < 4) ? (Bh + (size_t)n * ldb + k0 + c * 8)
                                      : (Bl + (size_t)n * ldb + k0 + (c - 4) * 8);
            cp16(dst, src);
        }
        cp_commit();
    };

    const int NC = K / BK;
    load_stage(0, 0);
    if (NC > 1) load_stage(1, BK);

    for (int c = 0; c < NC; c++) {
        if (c + 1 < NC) asm volatile("cp.async.wait_group 1;" ::: "memory");
        else            asm volatile("cp.async.wait_group 0;" ::: "memory");
        __syncthreads();
        if (c + 2 < NC) load_stage((c + 2) % 3, (c + 2) * BK);

        uint32_t sbc = sb + (c % 3) * STAGE;
#pragma unroll
        for (int step = 0; step < 2; step++) {
            uint32_t x = step << 5;             // ks=16 -> chunk XOR 32
            uint32_t aH[2][4], bH[4][2];
            LDSM4(aH[0][0], aH[0][1], aH[0][2], aH[0][3], (sbc + offA[0]) ^ x);
            LDSM4(aH[1][0], aH[1][1], aH[1][2], aH[1][3], (sbc + offA[1]) ^ x);
            LDSM4(bH[0][0], bH[0][1], bH[1][0], bH[1][1], (sbc + offB[0]) ^ x);
            LDSM4(bH[2][0], bH[2][1], bH[3][0], bH[3][1], (sbc + offB[1]) ^ x);
#pragma unroll
            for (int i = 0; i < 2; i++)
#pragma unroll
                for (int j = 0; j < 4; j++) MMA16816(acc[i][j], aH[i], bH[j]);

            uint32_t aL[2][4];
            LDSM4(aL[0][0], aL[0][1], aL[0][2], aL[0][3], (sbc + offA[0]) ^ (x | 64u));
            LDSM4(aL[1][0], aL[1][1], aL[1][2], aL[1][3], (sbc + offA[1]) ^ (x | 64u));
#pragma unroll
            for (int i = 0; i < 2; i++)
#pragma unroll
                for (int j = 0; j < 4; j++) MMA16816(acc[i][j], aL[i], bH[j]);

            uint32_t bL[4][2];
            LDSM4(bL[0][0], bL[0][1], bL[1][0], bL[1][1], (sbc + offB[0]) ^ (x | 64u));
            LDSM4(bL[2][0], bL[2][1], bL[3][0], bL[3][1], (sbc + offB[1]) ^ (x | 64u));
#pragma unroll
            for (int i = 0; i < 2; i++)
#pragma unroll
                for (int j = 0; j < 4; j++) MMA16816(acc[i][j], aH[i], bL[j]);
        }
        __syncthreads();
    }

    // ---------------- epilogue: stage fp32 tile, then coalesced store --------
    float* stg = (float*)sm;
#pragma unroll
    for (int i = 0; i < 2; i++)
#pragma unroll
        for (int j = 0; j < 4; j++) {
            int row = wm * 32 + 16 * i + g, col = wn * 32 + 8 * j + 2 * t;
            float c0 = acc[i][j][0], c1 = acc[i][j][1];
            float c2 = acc[i][j][2], c3 = acc[i][j][3];
            if (EPI == 2) {
                c0 = __expf(c0 * 0.03125f); c1 = __expf(c1 * 0.03125f);
                c2 = __expf(c2 * 0.03125f); c3 = __expf(c3 * 0.03125f);
            }
            stg[row * CSTR + col]           = c0;
            stg[row * CSTR + col + 1]       = c1;
            stg[(row + 8) * CSTR + col]     = c2;
            stg[(row + 8) * CSTR + col + 1] = c3;
        }
    __syncthreads();

    if (EPI == 2 && tid < 64) {
        float s = 0.f;
#pragma unroll 8
        for (int r = 0; r < 128; r++) s += stg[r * CSTR + tid];
        atomicAdd(rs + (size_t)blockIdx.z * SS + n0 + tid, s);
    }
    {
        int row = tid >> 1, cb = (tid & 1) * 32;
        size_t cof = (size_t)zb * sCb + (size_t)zh * sCh + (size_t)(m0 + row) * ldc + n0 + cb;
        if (EPI == 0) {
            float* dst = Cf + cof;
#pragma unroll
            for (int e = 0; e < 8; e++)
                *(float4*)(dst + e * 4) = *(float4*)&stg[row * CSTR + cb + e * 4];
        } else {
            uint32_t hw[16], lw[16];
#pragma unroll
            for (int e = 0; e < 16; e++) {
                float f0 = stg[row * CSTR + cb + 2 * e];
                float f1 = stg[row * CSTR + cb + 2 * e + 1];
                bf16 h0, l0, h1, l1;
                fsplit(f0, h0, l0);
                fsplit(f1, h1, l1);
                hw[e] = pack2(h0, h1);
                lw[e] = pack2(l0, l1);
            }
#pragma unroll
            for (int e = 0; e < 4; e++) {
                *(uint4*)(Chi + cof + 8 * e) =
                    make_uint4(hw[4 * e], hw[4 * e + 1], hw[4 * e + 2], hw[4 * e + 3]);
                *(uint4*)(Clo + cof + 8 * e) =
                    make_uint4(lw[4 * e], lw[4 * e + 1], lw[4 * e + 2], lw[4 * e + 3]);
            }
        }
    }
}

// ---------------- prep / elementwise kernels ----------------------------------
__global__ void splitf_k(const float* __restrict__ in, bf16* __restrict__ hi,
                         bf16* __restrict__ lo) {
    size_t i = ((size_t)blockIdx.x * 256 + threadIdx.x) * 4;
    float4 v = *(const float4*)(in + i);
    bf16 h0, l0, h1, l1, h2, l2, h3, l3;
    fsplit(v.x, h0, l0); fsplit(v.y, h1, l1);
    fsplit(v.z, h2, l2); fsplit(v.w, h3, l3);
    *(uint2*)(hi + i) = make_uint2(pack2(h0, h1), pack2(h2, h3));
    *(uint2*)(lo + i) = make_uint2(pack2(l0, l1), pack2(l2, l3));
}

__global__ void wprep_k(const float* __restrict__ W, bf16* __restrict__ Thi,
                        bf16* __restrict__ Tlo) {
    __shared__ float t[32][33];
    int x = blockIdx.x * 32 + threadIdx.x;
    int y = blockIdx.y * 32 + threadIdx.y;
#pragma unroll
    for (int i = 0; i < 32; i += 8)
        t[threadIdx.y + i][threadIdx.x] = W[(size_t)(y + i) * DD + x];
    __syncthreads();
    x = blockIdx.y * 32 + threadIdx.x;
    y = blockIdx.x * 32 + threadIdx.y;
#pragma unroll
    for (int i = 0; i < 32; i += 8) {
        bf16 h, l;
        fsplit(t[threadIdx.x][threadIdx.y + i], h, l);
        Thi[(size_t)(y + i) * DD + x] = h;
        Tlo[(size_t)(y + i) * DD + x] = l;
    }
}

__global__ void zero_k(float* __restrict__ p, int n) {
    int i = blockIdx.x * 256 + threadIdx.x;
    if (i < n) p[i] = 0.f;
}

// V'[bh][v][k] = V[b][k][h*64+v] / rs[bh][k], split into hi/lo bf16
__global__ void __launch_bounds__(256) vprep_k(const float* __restrict__ v,
                                               const float* __restrict__ rs,
                                               bf16* __restrict__ vthi,
                                               bf16* __restrict__ vtlo) {
    int bh = blockIdx.y, b = bh >> 4, h = bh & 15, k0 = blockIdx.x * 64;
    __shared__ float t[64][65];
    __shared__ float rsi[64];
    int tid = threadIdx.x;
    if (tid < 64) rsi[tid] = 1.0f / rs[(size_t)bh * SS + k0 + tid];
    __syncthreads();
    for (int e = tid; e < 4096; e += 256) {
        int kk = e >> 6, vv = e & 63;
        t[kk][vv] = v[((size_t)(b * SS + k0 + kk)) * DD + h * 64 + vv] * rsi[kk];
    }
    __syncthreads();
    for (int e = tid; e < 4096; e += 256) {
        int vv = e >> 6, kk = e & 63;
        bf16 hh, ll;
        fsplit(t[kk][vv], hh, ll);
        size_t o = (size_t)bh * 64 * SS + (size_t)vv * SS + k0 + kk;
        vthi[o] = hh;
        vtlo[o] = ll;
    }
}

__global__ __launch_bounds__(256) void l2nsplit_k(const float* __restrict__ in,
                                                  bf16* __restrict__ ohi,
                                                  bf16* __restrict__ olo) {
    size_t row = blockIdx.x;
    const float* p = in + row * (size_t)DD;
    int tid = threadIdx.x;
    float4 v = *(const float4*)(p + tid * 4);
    float ss = v.x * v.x + v.y * v.y + v.z * v.z + v.w * v.w;
    __shared__ float red[256];
    red[tid] = ss; __syncthreads();
    for (int s2 = 128; s2 > 0; s2 >>= 1) {
        if (tid < s2) red[tid] += red[tid + s2];
        __syncthreads();
    }
    float inv = 1.0f / fmaxf(sqrtf(red[0]), 1e-12f);
    bf16 h0, l0, h1, l1, h2, l2, h3, l3;
    fsplit(v.x * inv, h0, l0); fsplit(v.y * inv, h1, l1);
    fsplit(v.z * inv, h2, l2); fsplit(v.w * inv, h3, l3);
    *(uint2*)(ohi + row * DD + tid * 4) = make_uint2(pack2(h0, h1), pack2(h2, h3));
    *(uint2*)(olo + row * DD + tid * 4) = make_uint2(pack2(l0, l1), pack2(l2, l3));
}

__device__ __forceinline__ float gelu_exact(float x) {
    return 0.5f * x * (1.0f + erff(x * 0.7071067811865475f));
}

__global__ __launch_bounds__(256) void l2ngelu_k(const float* __restrict__ in,
                                                 float* __restrict__ out) {
    size_t row = blockIdx.x;
    const float* p = in + row * (size_t)DD;
    int tid = threadIdx.x;
    float4 v = *(const float4*)(p + tid * 4);
    float ss = v.x * v.x + v.y * v.y + v.z * v.z + v.w * v.w;
    __shared__ float red[256];
    red[tid] = ss; __syncthreads();
    for (int s2 = 128; s2 > 0; s2 >>= 1) {
        if (tid < s2) red[tid] += red[tid + s2];
        __syncthreads();
    }
    float inv = 1.0f / fmaxf(sqrtf(red[0]), 1e-12f);
    *(float4*)(out + row * DD + tid * 4) =
        make_float4(gelu_exact(v.x * inv), gelu_exact(v.y * inv),
                    gelu_exact(v.z * inv), gelu_exact(v.w * inv));
}

// ---------------- launch ------------------------------------------------------
extern "C" void kernel_launch(void* const* d_in, const int* in_sizes, int n_in,
                              void* d_out, int out_size)
{
    const float* x = (const float*)d_in[0];
    const float* W[5] = {(const float*)d_in[1], (const float*)d_in[2], (const float*)d_in[3],
                         (const float*)d_in[4], (const float*)d_in[5]};
    float* out = (float*)d_out;

    bf16 *xhi, *xlo, *wthi, *wtlo, *qhi, *qlo, *khi, *klo;
    bf16 *ehi, *elo, *vthi, *vtlo, *z1hi, *z1lo, *z2hi, *z2lo;
    float *f1, *f2, *rs;
    cudaGetSymbolAddress((void**)&xhi, g_xhi);   cudaGetSymbolAddress((void**)&xlo, g_xlo);
    cudaGetSymbolAddress((void**)&wthi, g_wthi); cudaGetSymbolAddress((void**)&wtlo, g_wtlo);
    cudaGetSymbolAddress((void**)&qhi, g_qhi);   cudaGetSymbolAddress((void**)&qlo, g_qlo);
    cudaGetSymbolAddress((void**)&khi, g_khi);   cudaGetSymbolAddress((void**)&klo, g_klo);
    cudaGetSymbolAddress((void**)&ehi, g_ehi);   cudaGetSymbolAddress((void**)&elo, g_elo);
    cudaGetSymbolAddress((void**)&vthi, g_vthi); cudaGetSymbolAddress((void**)&vtlo, g_vtlo);
    cudaGetSymbolAddress((void**)&z1hi, g_z1hi); cudaGetSymbolAddress((void**)&z1lo, g_z1lo);
    cudaGetSymbolAddress((void**)&z2hi, g_z2hi); cudaGetSymbolAddress((void**)&z2lo, g_z2lo);
    cudaGetSymbolAddress((void**)&f1, g_f1);     cudaGetSymbolAddress((void**)&f2, g_f2);
    cudaGetSymbolAddress((void**)&rs, g_rs);

    cudaFuncSetAttribute(mma_gemm<0>, cudaFuncAttributeMaxDynamicSharedMemorySize, SMM);
    cudaFuncSetAttribute(mma_gemm<1>, cudaFuncAttributeMaxDynamicSharedMemorySize, SMM);
    cudaFuncSetAttribute(mma_gemm<2>, cudaFuncAttributeMaxDynamicSharedMemorySize, SMM);

    const size_t WSTEP = (size_t)DD * DD;

    // prep: split x, transpose+split weights, zero rs
    splitf_k<<<NTOK * DD / 1024, 256>>>(x, xhi, xlo);
    dim3 tb(32, 8), tg(32, 32);
    for (int i = 0; i < 5; i++)
        wprep_k<<<tg, tb>>>(W[i], wthi + i * WSTEP, wtlo + i * WSTEP);
    zero_k<<<BHN * SS / 256, 256>>>(rs, BHN * SS);

    // QKV projections (q,k split outputs; v fp32)
    dim3 gnn(16, 32, 1);
    mma_gemm<1><<<gnn, 256, SMM>>>(xhi, xlo, DD, 0, 0,
                                   wthi + 0 * WSTEP, wtlo + 0 * WSTEP, DD, 0, 0,
                                   nullptr, qhi, qlo, DD, 0, 0, DD, nullptr);
    mma_gemm<1><<<gnn, 256, SMM>>>(xhi, xlo, DD, 0, 0,
                                   wthi + 1 * WSTEP, wtlo + 1 * WSTEP, DD, 0, 0,
                                   nullptr, khi, klo, DD, 0, 0, DD, nullptr);
    mma_gemm<0><<<gnn, 256, SMM>>>(xhi, xlo, DD, 0, 0,
                                   wthi + 2 * WSTEP, wtlo + 2 * WSTEP, DD, 0, 0,
                                   f1, nullptr, nullptr, DD, 0, 0, DD, nullptr);

    // E^T[bh][q][k] = exp(q.k/32), col sums -> rs[bh][k]
    dim3 gsc(SS / BN, SS / BM, BHN);   // (32, 16, 32)
    mma_gemm<2><<<gsc, 256, SMM>>>(qhi, qlo, DD, (size_t)SS * DD, 64,
                                   khi, klo, DD, (size_t)SS * DD, 64,
                                   nullptr, ehi, elo, SS,
                                   (size_t)16 * SS * SS, (size_t)SS * SS,
                                   64, rs);

    // V' = V / rs (transposed, split)
    vprep_k<<<dim3(SS / 64, BHN), 256>>>(f1, rs, vthi, vtlo);

    // z1[q, h*64+v] = sum_k E^T[q,k] * V'[v,k]
    dim3 gao(1, SS / BM, BHN);         // (1, 16, 32)
    mma_gemm<1><<<gao, 256, SMM>>>(ehi, elo, SS, (size_t)16 * SS * SS, (size_t)SS * SS,
                                   vthi, vtlo, SS, (size_t)16 * 64 * SS, (size_t)64 * SS,
                                   nullptr, z1hi, z1lo, DD, (size_t)SS * DD, 64,
                                   SS, nullptr);

    // output projection -> z2 (fp32), normalize+split, FF -> z3 (fp32), norm+gelu
    mma_gemm<0><<<gnn, 256, SMM>>>(z1hi, z1lo, DD, 0, 0,
                                   wthi + 3 * WSTEP, wtlo + 3 * WSTEP, DD, 0, 0,
                                   f2, nullptr, nullptr, DD, 0, 0, DD, nullptr);
    l2nsplit_k<<<NTOK, 256>>>(f2, z2hi, z2lo);
    mma_gemm<0><<<gnn, 256, SMM>>>(z2hi, z2lo, DD, 0, 0,
                                   wthi + 4 * WSTEP, wtlo + 4 * WSTEP, DD, 0, 0,
                                   f1, nullptr, nullptr, DD, 0, 0, DD, nullptr);
    l2ngelu_k<<<NTOK, 256>>>(f1, out);
}